// round 1
// baseline (speedup 1.0000x reference)
#include <cuda_runtime.h>
#include <math.h>

// Problem constants
#define BB 2
#define CC 48
#define HH 64
#define WW 64
#define NN 4096
#define RPE_S 191

// ---------------- scratch (device globals; no allocation allowed) -------------
__device__ float g_q  [BB*CC*NN];   // q = Wq x + bq             (B,48,n)
__device__ float g_x2 [BB*96*NN];   // BN(inp conv)              (B,96,n)
__device__ float g_pos[BB*NN*2];    // sampling positions (y,x)  (B,n,2)
__device__ float g_xs [BB*CC*NN];   // grid-sampled x            (B,48,n)
__device__ float g_k  [BB*CC*NN];
__device__ float g_v  [BB*CC*NN];
__device__ float g_od [BB*CC*NN];   // deformable-attention output
__device__ float g_win[BB*CC*NN];   // window-attention output

// ---------------- helpers -----------------------------------------------------
__device__ __forceinline__ float bilin(const float* __restrict__ img, int H, int W,
                                       float gx, float gy) {
    float x0f = floorf(gx), y0f = floorf(gy);
    int   x0  = (int)x0f,   y0  = (int)y0f;
    float wx  = gx - x0f,   wy  = gy - y0f;
    float acc = 0.f;
#pragma unroll
    for (int dy = 0; dy < 2; dy++) {
        int yc = y0 + dy;
        if (yc < 0 || yc >= H) continue;
        float wyv = dy ? wy : (1.f - wy);
#pragma unroll
        for (int dx = 0; dx < 2; dx++) {
            int xc = x0 + dx;
            if (xc < 0 || xc >= W) continue;
            float wxv = dx ? wx : (1.f - wx);
            acc += img[yc * W + xc] * (wyv * wxv);
        }
    }
    return acc;
}

// ---------------- 1x1 conv: q = Wq x + bq -> g_q ------------------------------
__global__ void conv_q_kernel(const float* __restrict__ x, const float* __restrict__ W,
                              const float* __restrict__ bias) {
    int idx = blockIdx.x * 256 + threadIdx.x;
    if (idx >= BB * CC * NN) return;
    int p = idx & (NN - 1);
    int o = (idx >> 12) % CC;
    int b = idx / (CC * NN);
    float acc = bias[o];
    const float* xb = x + b * CC * NN + p;
    const float* wr = W + o * CC;
#pragma unroll 8
    for (int c = 0; c < CC; c++) acc += wr[c] * xb[c * NN];
    g_q[idx] = acc;
}

// ---------------- 1x1 conv (96ch) + BN -> g_x2 --------------------------------
__global__ void conv_x2_kernel(const float* __restrict__ x, const float* __restrict__ W,
                               const float* __restrict__ bias,
                               const float* __restrict__ bng, const float* __restrict__ bnb,
                               const float* __restrict__ bnm, const float* __restrict__ bnv) {
    int idx = blockIdx.x * 256 + threadIdx.x;
    if (idx >= BB * 96 * NN) return;
    int p = idx & (NN - 1);
    int o = (idx >> 12) % 96;
    int b = idx / (96 * NN);
    float acc = bias[o];
    const float* xb = x + b * CC * NN + p;
    const float* wr = W + o * CC;
#pragma unroll 8
    for (int c = 0; c < CC; c++) acc += wr[c] * xb[c * NN];
    acc = (acc - bnm[o]) * rsqrtf(bnv[o] + 1e-5f) * bng[o] + bnb[o];
    g_x2[idx] = acc;
}

// ---------------- offset head + position + grid-sample x ----------------------
// one block per (batch, image row); 256 threads
__global__ void deform_kernel(const float* __restrict__ x,
                              const float* __restrict__ dww, const float* __restrict__ dwb,
                              const float* __restrict__ lng, const float* __restrict__ lnb,
                              const float* __restrict__ pww) {
    int b = blockIdx.y;
    int y = blockIdx.x;
    int tid = threadIdx.x;
    __shared__ float ts[CC * WW];      // t values for this row: [c][px]
    __shared__ float posr[WW * 2];

    // depthwise 3x3 conv on q
    for (int i = tid; i < CC * WW; i += 256) {
        int c = i >> 6, px = i & 63;
        float acc = dwb[c];
        const float* qc = g_q + (b * CC + c) * NN;
        const float* wc = dww + c * 9;
#pragma unroll
        for (int ky = 0; ky < 3; ky++) {
            int yy = y + ky - 1;
            if (yy < 0 || yy > 63) continue;
#pragma unroll
            for (int kx = 0; kx < 3; kx++) {
                int xx = px + kx - 1;
                if (xx < 0 || xx > 63) continue;
                acc += qc[(yy << 6) + xx] * wc[ky * 3 + kx];
            }
        }
        ts[c * 64 + px] = acc;
    }
    __syncthreads();

    // per-pixel channel LN + exact GELU + 2-ch offset head + tanh -> pos
    if (tid < WW) {
        int px = tid;
        float mu = 0.f;
        for (int c = 0; c < CC; c++) mu += ts[c * 64 + px];
        mu *= (1.f / CC);
        float var = 0.f;
        for (int c = 0; c < CC; c++) { float d = ts[c * 64 + px] - mu; var += d * d; }
        var *= (1.f / CC);
        float rs = rsqrtf(var + 1e-5f);
        float a0 = 0.f, a1 = 0.f;
        for (int c = 0; c < CC; c++) {
            float v = (ts[c * 64 + px] - mu) * rs * lng[c] + lnb[c];
            v = 0.5f * v * (1.f + erff(v * 0.7071067811865475f));   // exact gelu
            a0 += pww[c] * v;          // offset channel 0 (y)
            a1 += pww[CC + c] * v;     // offset channel 1 (x)
        }
        float py  = tanhf(a0) * (2.f / 63.f) + ((0.5f + (float)y ) * (2.f / 63.f) - 1.f);
        float pxx = tanhf(a1) * (2.f / 63.f) + ((0.5f + (float)px) * (2.f / 63.f) - 1.f);
        posr[px * 2 + 0] = py;
        posr[px * 2 + 1] = pxx;
        int n = (y << 6) + px;
        g_pos[(b * NN + n) * 2 + 0] = py;
        g_pos[(b * NN + n) * 2 + 1] = pxx;
    }
    __syncthreads();

    // bilinear sample of x at pos (zero padding)
    for (int i = tid; i < CC * WW; i += 256) {
        int c = i >> 6, px = i & 63;
        float py  = posr[px * 2 + 0];
        float pxx = posr[px * 2 + 1];
        float gx = (pxx + 1.f) * 0.5f * 63.f;
        float gy = (py  + 1.f) * 0.5f * 63.f;
        const float* img = x + (b * CC + c) * NN;
        g_xs[(b * CC + c) * NN + (y << 6) + px] = bilin(img, HH, WW, gx, gy);
    }
}

// ---------------- k,v projections from sampled x -------------------------------
__global__ void conv_kv_kernel(const float* __restrict__ Wk, const float* __restrict__ bk,
                               const float* __restrict__ Wv, const float* __restrict__ bv) {
    int idx = blockIdx.x * 256 + threadIdx.x;
    if (idx >= BB * CC * NN) return;
    int p = idx & (NN - 1);
    int o = (idx >> 12) % CC;
    int b = idx / (CC * NN);
    float ak = bk[o], av = bv[o];
    const float* xb = g_xs + b * CC * NN + p;
    const float* wkr = Wk + o * CC;
    const float* wvr = Wv + o * CC;
#pragma unroll 8
    for (int c = 0; c < CC; c++) {
        float xv = xb[c * NN];
        ak += wkr[c] * xv;
        av += wvr[c] * xv;
    }
    g_k[idx] = ak;
    g_v[idx] = av;
}

// ---------------- fused flash attention with RPE bias -------------------------
// block: 32 queries x full key loop in 64-key tiles, 256 threads
__global__ void __launch_bounds__(256) attn_kernel(const float* __restrict__ rpe) {
    const int b   = blockIdx.y;
    const int m0  = blockIdx.x * 32;
    const int tid = threadIdx.x;
    const int m   = tid >> 3;     // 0..31 query within tile
    const int l8  = tid & 7;      // 8 threads cooperate per query
    const int cb  = l8 * 6;       // 6 output channels per thread

    __shared__ float qs[32][49];
    __shared__ float kv[64][49];
    __shared__ float Ss[32][65];
    __shared__ float pk[128];     // (y,x) per key

    const float scale = 0.14433756729740643f;   // 1/sqrt(48)

    for (int i = tid; i < 32 * CC; i += 256) {
        int c = i >> 5, mi = i & 31;
        qs[mi][c] = g_q[(b * CC + c) * NN + m0 + mi] * scale;
    }

    const int mq = m0 + m;
    const float qy = (float)(mq >> 6) * (2.f / 63.f) - 1.f;
    const float qx = (float)(mq & 63) * (2.f / 63.f) - 1.f;

    float rmax = -1e30f, rsum = 0.f;
    float o[6] = {0.f, 0.f, 0.f, 0.f, 0.f, 0.f};

    for (int n0 = 0; n0 < NN; n0 += 64) {
        __syncthreads();
        for (int i = tid; i < 64 * CC; i += 256) {
            int c = i >> 6, ni = i & 63;
            kv[ni][c] = g_k[(b * CC + c) * NN + n0 + ni];
        }
        if (tid < 128) pk[tid] = g_pos[(b * NN + n0) * 2 + tid];
        __syncthreads();

        float sv[8];
        float tmax = -1e30f;
#pragma unroll
        for (int i = 0; i < 8; i++) {
            int nn = l8 * 8 + i;
            float dot = 0.f;
#pragma unroll
            for (int c = 0; c < CC; c++) dot += qs[m][c] * kv[nn][c];
            float dy = (qy - pk[nn * 2 + 0]) * 0.5f;
            float dx = (qx - pk[nn * 2 + 1]) * 0.5f;
            float bias = bilin(rpe, RPE_S, RPE_S, (dx + 1.f) * 95.f, (dy + 1.f) * 95.f);
            float s = dot + bias;
            sv[i] = s;
            tmax = fmaxf(tmax, s);
        }
#pragma unroll
        for (int w = 1; w < 8; w <<= 1)
            tmax = fmaxf(tmax, __shfl_xor_sync(0xffffffffu, tmax, w));

        float nmax = fmaxf(rmax, tmax);
        float f = __expf(rmax - nmax);
        float ps = 0.f;
#pragma unroll
        for (int i = 0; i < 8; i++) {
            float p = __expf(sv[i] - nmax);
            Ss[m][l8 * 8 + i] = p;
            ps += p;
        }
#pragma unroll
        for (int w = 1; w < 8; w <<= 1)
            ps += __shfl_xor_sync(0xffffffffu, ps, w);
        rsum = rsum * f + ps;
        rmax = nmax;
#pragma unroll
        for (int j = 0; j < 6; j++) o[j] *= f;

        __syncthreads();
        for (int i = tid; i < 64 * CC; i += 256) {
            int c = i >> 6, ni = i & 63;
            kv[ni][c] = g_v[(b * CC + c) * NN + n0 + ni];
        }
        __syncthreads();

        for (int nn = 0; nn < 64; nn++) {
            float p = Ss[m][nn];
#pragma unroll
            for (int j = 0; j < 6; j++) o[j] += p * kv[nn][cb + j];
        }
    }

    float inv = 1.f / rsum;
#pragma unroll
    for (int j = 0; j < 6; j++)
        g_od[(b * CC + cb + j) * NN + m0 + m] = o[j] * inv;
}

// ---------------- window attention (3 splits x 64 windows x B) -----------------
__global__ void winattn_kernel() {
    int b  = blockIdx.z;
    int sp = blockIdx.y;      // split 0,1,2
    int w  = blockIdx.x;      // window 0..63
    int t  = threadIdx.x;     // token 0..63

    __shared__ float qsm[64][17];
    __shared__ float vsm[64][17];

    int py, px;
    if (sp == 0)      { int wy = w >> 3, wx = w & 7; py = wy * 8 + (t >> 3); px = wx * 8 + (t & 7); }
    else if (sp == 1) { py = t;  px = w; }
    else              { py = w;  px = t; }
    int pix = py * 64 + px;

    int qbase = (b * 96 + sp * 32) * NN + pix;
#pragma unroll
    for (int c = 0; c < 16; c++) {
        qsm[t][c] = g_x2[qbase + c * NN];
        vsm[t][c] = g_x2[qbase + (16 + c) * NN];
    }
    __syncthreads();

    float qr[16];
#pragma unroll
    for (int c = 0; c < 16; c++) qr[c] = qsm[t][c];

    float lg[64];
    float mx = -1e30f;
    for (int j = 0; j < 64; j++) {
        float d = 0.f;
#pragma unroll
        for (int c = 0; c < 16; c++) d += qr[c] * qsm[j][c];
        lg[j] = d;
        mx = fmaxf(mx, d);
    }
    float s = 0.f;
    for (int j = 0; j < 64; j++) { lg[j] = __expf(lg[j] - mx); s += lg[j]; }
    float inv = 1.f / s;

    float o[16];
#pragma unroll
    for (int c = 0; c < 16; c++) o[c] = 0.f;
    for (int j = 0; j < 64; j++) {
        float p = lg[j] * inv;
#pragma unroll
        for (int c = 0; c < 16; c++) o[c] += p * vsm[j][c];
    }
#pragma unroll
    for (int c = 0; c < 16; c++)
        g_win[(b * CC + sp * 16 + c) * NN + pix] = o[c];
}

// ---------------- final: pout conv on window branch + average ------------------
__global__ void final_kernel(const float* __restrict__ pw, const float* __restrict__ pb,
                             float* __restrict__ out) {
    int idx = blockIdx.x * 256 + threadIdx.x;
    if (idx >= BB * CC * NN) return;
    int p = idx & (NN - 1);
    int o = (idx >> 12) % CC;
    int b = idx / (CC * NN);
    float acc = pb[o];
    const float* wb = g_win + b * CC * NN + p;
    const float* wr = pw + o * CC;
#pragma unroll 8
    for (int c = 0; c < CC; c++) acc += wr[c] * wb[c * NN];
    out[idx] = 0.5f * acc + 0.5f * g_od[idx];
}

// ---------------- launch -------------------------------------------------------
extern "C" void kernel_launch(void* const* d_in, const int* in_sizes, int n_in,
                              void* d_out, int out_size) {
    const float* x        = (const float*)d_in[0];
    const float* Wq       = (const float*)d_in[1];
    const float* bq       = (const float*)d_in[2];
    const float* off_dw_w = (const float*)d_in[3];
    const float* off_dw_b = (const float*)d_in[4];
    const float* off_ln_g = (const float*)d_in[5];
    const float* off_ln_b = (const float*)d_in[6];
    const float* off_pw_w = (const float*)d_in[7];
    const float* Wk       = (const float*)d_in[8];
    const float* bk       = (const float*)d_in[9];
    const float* Wv       = (const float*)d_in[10];
    const float* bv       = (const float*)d_in[11];
    const float* inp_w    = (const float*)d_in[12];
    const float* inp_b    = (const float*)d_in[13];
    const float* bn_g     = (const float*)d_in[14];
    const float* bn_b     = (const float*)d_in[15];
    const float* bn_mean  = (const float*)d_in[16];
    const float* bn_var   = (const float*)d_in[17];
    const float* pout_w   = (const float*)d_in[18];
    const float* pout_b   = (const float*)d_in[19];
    const float* rpe      = (const float*)d_in[20];
    float* out = (float*)d_out;

    conv_q_kernel<<<(BB * CC * NN + 255) / 256, 256>>>(x, Wq, bq);
    conv_x2_kernel<<<(BB * 96 * NN + 255) / 256, 256>>>(x, inp_w, inp_b,
                                                        bn_g, bn_b, bn_mean, bn_var);
    deform_kernel<<<dim3(HH, BB), 256>>>(x, off_dw_w, off_dw_b,
                                         off_ln_g, off_ln_b, off_pw_w);
    conv_kv_kernel<<<(BB * CC * NN + 255) / 256, 256>>>(Wk, bk, Wv, bv);
    attn_kernel<<<dim3(NN / 32, BB), 256>>>(rpe);
    winattn_kernel<<<dim3(64, 3, BB), 64>>>();
    final_kernel<<<(BB * CC * NN + 255) / 256, 256>>>(pout_w, pout_b, out);
}

// round 2
// speedup vs baseline: 2.3259x; 2.3259x over previous
#include <cuda_runtime.h>
#include <math.h>

// Problem constants
#define BB 2
#define CC 48
#define HH 64
#define WW 64
#define NN 4096
#define RPE_S 191
#define NSPLIT 2
#define KEYS_PER_SPLIT (NN / NSPLIT)

// ---------------- scratch (device globals; no allocation allowed) -------------
__device__ float g_q  [BB*CC*NN];        // q = Wq x + bq             (B,48,n)
__device__ float g_x2 [BB*96*NN];        // BN(inp conv)              (B,96,n)
__device__ float g_pos[BB*NN*2];         // sampling positions (y,x)  (B,n,2)
__device__ float g_xs [BB*CC*NN];        // grid-sampled x            (B,48,n)
__device__ float g_k  [BB*CC*NN];
__device__ float g_v  [BB*CC*NN];
__device__ float g_win[BB*CC*NN];        // window-attention output
__device__ float g_opart[NSPLIT*BB*CC*NN];  // split-KV partial outputs
__device__ float g_mpart[NSPLIT*BB*NN];
__device__ float g_lpart[NSPLIT*BB*NN];

// ---------------- helpers -----------------------------------------------------
__device__ __forceinline__ float bilin(const float* __restrict__ img, int H, int W,
                                       float gx, float gy) {
    float x0f = floorf(gx), y0f = floorf(gy);
    int   x0  = (int)x0f,   y0  = (int)y0f;
    float wx  = gx - x0f,   wy  = gy - y0f;
    float acc = 0.f;
#pragma unroll
    for (int dy = 0; dy < 2; dy++) {
        int yc = y0 + dy;
        if (yc < 0 || yc >= H) continue;
        float wyv = dy ? wy : (1.f - wy);
#pragma unroll
        for (int dx = 0; dx < 2; dx++) {
            int xc = x0 + dx;
            if (xc < 0 || xc >= W) continue;
            float wxv = dx ? wx : (1.f - wx);
            acc += img[yc * W + xc] * (wyv * wxv);
        }
    }
    return acc;
}

// ---------------- 1x1 conv: q = Wq x + bq -> g_q ------------------------------
__global__ void conv_q_kernel(const float* __restrict__ x, const float* __restrict__ W,
                              const float* __restrict__ bias) {
    int idx = blockIdx.x * 256 + threadIdx.x;
    if (idx >= BB * CC * NN) return;
    int p = idx & (NN - 1);
    int o = (idx >> 12) % CC;
    int b = idx / (CC * NN);
    float acc = bias[o];
    const float* xb = x + b * CC * NN + p;
    const float* wr = W + o * CC;
#pragma unroll 8
    for (int c = 0; c < CC; c++) acc += wr[c] * xb[c * NN];
    g_q[idx] = acc;
}

// ---------------- 1x1 conv (96ch) + BN -> g_x2 --------------------------------
__global__ void conv_x2_kernel(const float* __restrict__ x, const float* __restrict__ W,
                               const float* __restrict__ bias,
                               const float* __restrict__ bng, const float* __restrict__ bnb,
                               const float* __restrict__ bnm, const float* __restrict__ bnv) {
    int idx = blockIdx.x * 256 + threadIdx.x;
    if (idx >= BB * 96 * NN) return;
    int p = idx & (NN - 1);
    int o = (idx >> 12) % 96;
    int b = idx / (96 * NN);
    float acc = bias[o];
    const float* xb = x + b * CC * NN + p;
    const float* wr = W + o * CC;
#pragma unroll 8
    for (int c = 0; c < CC; c++) acc += wr[c] * xb[c * NN];
    acc = (acc - bnm[o]) * rsqrtf(bnv[o] + 1e-5f) * bng[o] + bnb[o];
    g_x2[idx] = acc;
}

// ---------------- offset head + position + grid-sample x ----------------------
__global__ void deform_kernel(const float* __restrict__ x,
                              const float* __restrict__ dww, const float* __restrict__ dwb,
                              const float* __restrict__ lng, const float* __restrict__ lnb,
                              const float* __restrict__ pww) {
    int b = blockIdx.y;
    int y = blockIdx.x;
    int tid = threadIdx.x;
    __shared__ float ts[CC * WW];
    __shared__ float posr[WW * 2];

    for (int i = tid; i < CC * WW; i += 256) {
        int c = i >> 6, px = i & 63;
        float acc = dwb[c];
        const float* qc = g_q + (b * CC + c) * NN;
        const float* wc = dww + c * 9;
#pragma unroll
        for (int ky = 0; ky < 3; ky++) {
            int yy = y + ky - 1;
            if (yy < 0 || yy > 63) continue;
#pragma unroll
            for (int kx = 0; kx < 3; kx++) {
                int xx = px + kx - 1;
                if (xx < 0 || xx > 63) continue;
                acc += qc[(yy << 6) + xx] * wc[ky * 3 + kx];
            }
        }
        ts[c * 64 + px] = acc;
    }
    __syncthreads();

    if (tid < WW) {
        int px = tid;
        float mu = 0.f;
        for (int c = 0; c < CC; c++) mu += ts[c * 64 + px];
        mu *= (1.f / CC);
        float var = 0.f;
        for (int c = 0; c < CC; c++) { float d = ts[c * 64 + px] - mu; var += d * d; }
        var *= (1.f / CC);
        float rs = rsqrtf(var + 1e-5f);
        float a0 = 0.f, a1 = 0.f;
        for (int c = 0; c < CC; c++) {
            float v = (ts[c * 64 + px] - mu) * rs * lng[c] + lnb[c];
            v = 0.5f * v * (1.f + erff(v * 0.7071067811865475f));
            a0 += pww[c] * v;
            a1 += pww[CC + c] * v;
        }
        float py  = tanhf(a0) * (2.f / 63.f) + ((0.5f + (float)y ) * (2.f / 63.f) - 1.f);
        float pxx = tanhf(a1) * (2.f / 63.f) + ((0.5f + (float)px) * (2.f / 63.f) - 1.f);
        posr[px * 2 + 0] = py;
        posr[px * 2 + 1] = pxx;
        int n = (y << 6) + px;
        g_pos[(b * NN + n) * 2 + 0] = py;
        g_pos[(b * NN + n) * 2 + 1] = pxx;
    }
    __syncthreads();

    for (int i = tid; i < CC * WW; i += 256) {
        int c = i >> 6, px = i & 63;
        float py  = posr[px * 2 + 0];
        float pxx = posr[px * 2 + 1];
        float gx = (pxx + 1.f) * 0.5f * 63.f;
        float gy = (py  + 1.f) * 0.5f * 63.f;
        const float* img = x + (b * CC + c) * NN;
        g_xs[(b * CC + c) * NN + (y << 6) + px] = bilin(img, HH, WW, gx, gy);
    }
}

// ---------------- k,v projections from sampled x -------------------------------
__global__ void conv_kv_kernel(const float* __restrict__ Wk, const float* __restrict__ bk,
                               const float* __restrict__ Wv, const float* __restrict__ bv) {
    int idx = blockIdx.x * 256 + threadIdx.x;
    if (idx >= BB * CC * NN) return;
    int p = idx & (NN - 1);
    int o = (idx >> 12) % CC;
    int b = idx / (CC * NN);
    float ak = bk[o], av = bv[o];
    const float* xb = g_xs + b * CC * NN + p;
    const float* wkr = Wk + o * CC;
    const float* wvr = Wv + o * CC;
#pragma unroll 8
    for (int c = 0; c < CC; c++) {
        float xv = xb[c * NN];
        ak += wkr[c] * xv;
        av += wvr[c] * xv;
    }
    g_k[idx] = ak;
    g_v[idx] = av;
}

// ---------------- fused flash attention with RPE bias (register tiled) --------
// block: 64 queries (= one image row) x 2048 keys (split-KV), 256 threads.
// S phase: thread = (kt = tid&15, mt = tid>>4), computes 4q x 4k tile.
// PV phase: thread = (ct = tid&15, mt = tid>>4), accumulates 4q x 3c.
__global__ void __launch_bounds__(256, 2) attn_kernel(const float* __restrict__ rpe) {
    const int y     = blockIdx.x;       // query row (64 queries m0..m0+63)
    const int split = blockIdx.y;
    const int b     = blockIdx.z;
    const int tid   = threadIdx.x;
    const int kt    = tid & 15;
    const int mt    = tid >> 4;
    const int m0    = y * 64;

    __shared__ __align__(16) float qsm[CC * 64];       // [c][m]
    __shared__ __align__(16) float kvbuf[64 * 49];     // k: [c][n] / v: [n][c]
    __shared__ __align__(16) float Ps[64 * 68];        // [n][m] padded
    __shared__ float kb_s[64];                         // 47.5*px per key
    __shared__ float wy0_s[64], wy1_s[64];
    __shared__ int   ry0_s[64], ry1_s[64];

    const float scale = 0.14433756729740643f;          // 1/sqrt(48)

    // load q tile (pre-scaled), layout [c][m]
    for (int i = tid; i < CC * 64; i += 256) {
        int c = i >> 6, m = i & 63;
        qsm[c * 64 + m] = g_q[(b * CC + c) * NN + m0 + m] * scale;
    }

    // per-query grid x coordinates: gxq = 47.5 + col * (95/63)
    float gxq[4];
#pragma unroll
    for (int mi = 0; mi < 4; mi++)
        gxq[mi] = 47.5f + (float)(mt * 4 + mi) * (95.0f / 63.0f);
    const float gyq = 47.5f + (float)y * (95.0f / 63.0f);

    float rmax[4], rsum[4], f[4];
    float o[4][3];
#pragma unroll
    for (int mi = 0; mi < 4; mi++) {
        rmax[mi] = -1e30f; rsum[mi] = 0.f;
#pragma unroll
        for (int j = 0; j < 3; j++) o[mi][j] = 0.f;
    }

    const int nbase = split * KEYS_PER_SPLIT;
    for (int t = 0; t < KEYS_PER_SPLIT / 64; t++) {
        const int n0 = nbase + t * 64;
        __syncthreads();   // prev PV done with Ps/kvbuf/keyaux

        // load K tile [c][n]
        for (int i = tid; i < CC * 64; i += 256) {
            int c = i >> 6, n = i & 63;
            kvbuf[c * 64 + n] = g_k[(b * CC + c) * NN + n0 + n];
        }
        // per-key aux: x base + y interpolation (qy constant for the block!)
        if (tid < 64) {
            float py = g_pos[(b * NN + n0 + tid) * 2 + 0];
            float px = g_pos[(b * NN + n0 + tid) * 2 + 1];
            kb_s[tid] = 47.5f * px;
            float gy = gyq - 47.5f * py;
            float yf = floorf(gy);
            float fy = gy - yf;
            int   iy = (int)yf;
            wy0_s[tid] = ((unsigned)iy       <= 190u) ? (1.f - fy) : 0.f;
            wy1_s[tid] = ((unsigned)(iy + 1) <= 190u) ? fy : 0.f;
            ry0_s[tid] = min(max(iy, 0), 190) * RPE_S;
            ry1_s[tid] = min(max(iy + 1, 0), 190) * RPE_S;
        }
        __syncthreads();

        // ---- S = qk + bias (4x4 register tile) ----
        float s[4][4];
#pragma unroll
        for (int a = 0; a < 4; a++)
#pragma unroll
            for (int bb2 = 0; bb2 < 4; bb2++) s[a][bb2] = 0.f;

#pragma unroll 8
        for (int c = 0; c < CC; c++) {
            float4 qv = *(const float4*)&qsm[c * 64 + mt * 4];
            float4 kv = *(const float4*)&kvbuf[c * 64 + kt * 4];
            s[0][0] += qv.x * kv.x; s[0][1] += qv.x * kv.y; s[0][2] += qv.x * kv.z; s[0][3] += qv.x * kv.w;
            s[1][0] += qv.y * kv.x; s[1][1] += qv.y * kv.y; s[1][2] += qv.y * kv.z; s[1][3] += qv.y * kv.w;
            s[2][0] += qv.z * kv.x; s[2][1] += qv.z * kv.y; s[2][2] += qv.z * kv.z; s[2][3] += qv.z * kv.w;
            s[3][0] += qv.w * kv.x; s[3][1] += qv.w * kv.y; s[3][2] += qv.w * kv.z; s[3][3] += qv.w * kv.w;
        }

        // ---- add RPE bias ----
#pragma unroll
        for (int ki = 0; ki < 4; ki++) {
            int n = kt * 4 + ki;
            float kb  = kb_s[n];
            float wy0 = wy0_s[n], wy1 = wy1_s[n];
            int   ry0 = ry0_s[n], ry1 = ry1_s[n];
#pragma unroll
            for (int mi = 0; mi < 4; mi++) {
                float gx = gxq[mi] - kb;
                float xf = floorf(gx);
                float fx = gx - xf;
                int   xi = (int)xf;
                float w0 = ((unsigned)xi       <= 190u) ? (1.f - fx) : 0.f;
                float w1 = ((unsigned)(xi + 1) <= 190u) ? fx : 0.f;
                int x0 = min(max(xi, 0), 190);
                int x1 = min(max(xi + 1, 0), 190);
                float b0 = rpe[ry0 + x0] * w0 + rpe[ry0 + x1] * w1;
                float b1 = rpe[ry1 + x0] * w0 + rpe[ry1 + x1] * w1;
                s[mi][ki] += wy0 * b0 + wy1 * b1;
            }
        }

        // ---- online softmax (reduce over kt: 16 lanes per query group) ----
#pragma unroll
        for (int mi = 0; mi < 4; mi++) {
            float tmax = fmaxf(fmaxf(s[mi][0], s[mi][1]), fmaxf(s[mi][2], s[mi][3]));
#pragma unroll
            for (int w = 1; w < 16; w <<= 1)
                tmax = fmaxf(tmax, __shfl_xor_sync(0xffffffffu, tmax, w));
            float nmax = fmaxf(rmax[mi], tmax);
            f[mi] = __expf(rmax[mi] - nmax);
            float p0 = __expf(s[mi][0] - nmax);
            float p1 = __expf(s[mi][1] - nmax);
            float p2 = __expf(s[mi][2] - nmax);
            float p3 = __expf(s[mi][3] - nmax);
            s[mi][0] = p0; s[mi][1] = p1; s[mi][2] = p2; s[mi][3] = p3;
            float ps = p0 + p1 + p2 + p3;
#pragma unroll
            for (int w = 1; w < 16; w <<= 1)
                ps += __shfl_xor_sync(0xffffffffu, ps, w);
            rsum[mi] = rsum[mi] * f[mi] + ps;
            rmax[mi] = nmax;
        }
        // write P transposed: Ps[n][m], float4 over m
#pragma unroll
        for (int ki = 0; ki < 4; ki++) {
            float4 pv = make_float4(s[0][ki], s[1][ki], s[2][ki], s[3][ki]);
            *(float4*)&Ps[(kt * 4 + ki) * 68 + mt * 4] = pv;
        }

        __syncthreads();    // S-phase reads of kvbuf done; Ps complete

        // load V tile into the same buffer, layout [n][c] (padded 49)
        for (int i = tid; i < CC * 64; i += 256) {
            int c = i >> 6, n = i & 63;
            kvbuf[n * 49 + c] = g_v[(b * CC + c) * NN + n0 + n];
        }
        __syncthreads();

        // ---- PV: thread = (ct = tid&15 -> 3 channels, mt -> 4 queries) ----
        const int ct = tid & 15;
#pragma unroll
        for (int mi = 0; mi < 4; mi++) {
#pragma unroll
            for (int j = 0; j < 3; j++) o[mi][j] *= f[mi];
        }
#pragma unroll 2
        for (int n = 0; n < 64; n++) {
            float4 p4 = *(const float4*)&Ps[n * 68 + mt * 4];
            float v0 = kvbuf[n * 49 + ct * 3 + 0];
            float v1 = kvbuf[n * 49 + ct * 3 + 1];
            float v2 = kvbuf[n * 49 + ct * 3 + 2];
            o[0][0] += p4.x * v0; o[0][1] += p4.x * v1; o[0][2] += p4.x * v2;
            o[1][0] += p4.y * v0; o[1][1] += p4.y * v1; o[1][2] += p4.y * v2;
            o[2][0] += p4.z * v0; o[2][1] += p4.z * v1; o[2][2] += p4.z * v2;
            o[3][0] += p4.w * v0; o[3][1] += p4.w * v1; o[3][2] += p4.w * v2;
        }
    }

    // ---- write partial results ----
    const int ct = tid & 15;
#pragma unroll
    for (int mi = 0; mi < 4; mi++) {
        int m = m0 + mt * 4 + mi;
#pragma unroll
        for (int j = 0; j < 3; j++) {
            int c = ct * 3 + j;
            g_opart[((split * BB + b) * CC + c) * NN + m] = o[mi][j];
        }
        if (ct == 0) {
            g_mpart[(split * BB + b) * NN + m] = rmax[mi];
            g_lpart[(split * BB + b) * NN + m] = rsum[mi];
        }
    }
}

// ---------------- window attention (3 splits x 64 windows x B) -----------------
__global__ void winattn_kernel() {
    int b  = blockIdx.z;
    int sp = blockIdx.y;
    int w  = blockIdx.x;
    int t  = threadIdx.x;

    __shared__ float qsm[64][17];
    __shared__ float vsm[64][17];

    int py, px;
    if (sp == 0)      { int wy = w >> 3, wx = w & 7; py = wy * 8 + (t >> 3); px = wx * 8 + (t & 7); }
    else if (sp == 1) { py = t;  px = w; }
    else              { py = w;  px = t; }
    int pix = py * 64 + px;

    int qbase = (b * 96 + sp * 32) * NN + pix;
#pragma unroll
    for (int c = 0; c < 16; c++) {
        qsm[t][c] = g_x2[qbase + c * NN];
        vsm[t][c] = g_x2[qbase + (16 + c) * NN];
    }
    __syncthreads();

    float qr[16];
#pragma unroll
    for (int c = 0; c < 16; c++) qr[c] = qsm[t][c];

    float lg[64];
    float mx = -1e30f;
    for (int j = 0; j < 64; j++) {
        float d = 0.f;
#pragma unroll
        for (int c = 0; c < 16; c++) d += qr[c] * qsm[j][c];
        lg[j] = d;
        mx = fmaxf(mx, d);
    }
    float s = 0.f;
    for (int j = 0; j < 64; j++) { lg[j] = __expf(lg[j] - mx); s += lg[j]; }
    float inv = 1.f / s;

    float o[16];
#pragma unroll
    for (int c = 0; c < 16; c++) o[c] = 0.f;
    for (int j = 0; j < 64; j++) {
        float p = lg[j] * inv;
#pragma unroll
        for (int c = 0; c < 16; c++) o[c] += p * vsm[j][c];
    }
#pragma unroll
    for (int c = 0; c < 16; c++)
        g_win[(b * CC + sp * 16 + c) * NN + pix] = o[c];
}

// ---------------- final: pout conv + split-KV merge + average ------------------
__global__ void final_kernel(const float* __restrict__ pw, const float* __restrict__ pb,
                             float* __restrict__ out) {
    int idx = blockIdx.x * 256 + threadIdx.x;
    if (idx >= BB * CC * NN) return;
    int p = idx & (NN - 1);
    int o = (idx >> 12) % CC;
    int b = idx / (CC * NN);
    float acc = pb[o];
    const float* wb = g_win + b * CC * NN + p;
    const float* wr = pw + o * CC;
#pragma unroll 8
    for (int c = 0; c < CC; c++) acc += wr[c] * wb[c * NN];

    // merge split-KV partials
    float m0v = g_mpart[(0 * BB + b) * NN + p];
    float m1v = g_mpart[(1 * BB + b) * NN + p];
    float M = fmaxf(m0v, m1v);
    float e0 = __expf(m0v - M), e1 = __expf(m1v - M);
    float l = g_lpart[(0 * BB + b) * NN + p] * e0 + g_lpart[(1 * BB + b) * NN + p] * e1;
    float od = (g_opart[((0 * BB + b) * CC + o) * NN + p] * e0 +
                g_opart[((1 * BB + b) * CC + o) * NN + p] * e1) / l;

    out[idx] = 0.5f * acc + 0.5f * od;
}

// ---------------- launch -------------------------------------------------------
extern "C" void kernel_launch(void* const* d_in, const int* in_sizes, int n_in,
                              void* d_out, int out_size) {
    const float* x        = (const float*)d_in[0];
    const float* Wq       = (const float*)d_in[1];
    const float* bq       = (const float*)d_in[2];
    const float* off_dw_w = (const float*)d_in[3];
    const float* off_dw_b = (const float*)d_in[4];
    const float* off_ln_g = (const float*)d_in[5];
    const float* off_ln_b = (const float*)d_in[6];
    const float* off_pw_w = (const float*)d_in[7];
    const float* Wk       = (const float*)d_in[8];
    const float* bk       = (const float*)d_in[9];
    const float* Wv       = (const float*)d_in[10];
    const float* bv       = (const float*)d_in[11];
    const float* inp_w    = (const float*)d_in[12];
    const float* inp_b    = (const float*)d_in[13];
    const float* bn_g     = (const float*)d_in[14];
    const float* bn_b     = (const float*)d_in[15];
    const float* bn_mean  = (const float*)d_in[16];
    const float* bn_var   = (const float*)d_in[17];
    const float* pout_w   = (const float*)d_in[18];
    const float* pout_b   = (const float*)d_in[19];
    const float* rpe      = (const float*)d_in[20];
    float* out = (float*)d_out;

    conv_q_kernel<<<(BB * CC * NN + 255) / 256, 256>>>(x, Wq, bq);
    conv_x2_kernel<<<(BB * 96 * NN + 255) / 256, 256>>>(x, inp_w, inp_b,
                                                        bn_g, bn_b, bn_mean, bn_var);
    deform_kernel<<<dim3(HH, BB), 256>>>(x, off_dw_w, off_dw_b,
                                         off_ln_g, off_ln_b, off_pw_w);
    conv_kv_kernel<<<(BB * CC * NN + 255) / 256, 256>>>(Wk, bk, Wv, bv);
    attn_kernel<<<dim3(64, NSPLIT, BB), 256>>>(rpe);
    winattn_kernel<<<dim3(64, 3, BB), 64>>>();
    final_kernel<<<(BB * CC * NN + 255) / 256, 256>>>(pout_w, pout_b, out);
}